// round 4
// baseline (speedup 1.0000x reference)
#include <cuda_runtime.h>
#include <cstdint>

// Problem constants (fixed shapes per reference)
#define N_SAMPLES 8192
#define I_BLOCK   256     // a-points per CTA (1 per thread)
#define K_CHUNK   512     // b-points per CTA chunk
#define N_IBLK    (N_SAMPLES / I_BLOCK)   // 32
#define N_KBLK    (N_SAMPLES / K_CHUNK)   // 16

// Scratch (no allocations allowed): gathered point tables + running min keys.
__device__ float4   g_pa[N_SAMPLES];   // (ax, ay, az, ||a||^2)
__device__ float4   g_pb[N_SAMPLES];   // (-2bx, -2by, -2bz, ||b||^2)
__device__ unsigned g_minkey[N_SAMPLES];

// Monotone uint key for float (total order matches float <, incl. negatives)
__device__ __forceinline__ unsigned fkey(float f) {
    unsigned u = __float_as_uint(f);
    return (u & 0x80000000u) ? ~u : (u | 0x80000000u);
}
__device__ __forceinline__ float funkey(unsigned k) {
    unsigned u = (k & 0x80000000u) ? (k & 0x7FFFFFFFu) : ~k;
    return __uint_as_float(u);
}

// ---------------------------------------------------------------------------
// Kernel 1: gather sampled points, pre-bake the fused-multiply forms,
//           and init the min-key array. Indices are int32 (JAX without x64
//           silently downgrades jnp.int64 -> int32).
// ---------------------------------------------------------------------------
__global__ void gather_init_kernel(const float* __restrict__ a,
                                   const float* __restrict__ b,
                                   const int* __restrict__ a_idx,
                                   const int* __restrict__ b_idx,
                                   int n_points) {
    int i = blockIdx.x * blockDim.x + threadIdx.x;
    if (i >= N_SAMPLES) return;

    int ia = a_idx[i];
    float ax = a[ia];
    float ay = a[n_points + ia];
    float az = a[2 * n_points + ia];
    g_pa[i] = make_float4(ax, ay, az, ax * ax + ay * ay + az * az);

    int ib = b_idx[i];
    float bx = b[ib];
    float by = b[n_points + ib];
    float bz = b[2 * n_points + ib];
    // v(i,k) = ||b_k||^2 - 2 * dot(b_k, a_i)  -> 3 FFMAs with these coeffs
    g_pb[i] = make_float4(-2.0f * bx, -2.0f * by, -2.0f * bz,
                          bx * bx + by * by + bz * bz);

    g_minkey[i] = 0xFFFFFFFFu;  // +max key
}

// ---------------------------------------------------------------------------
// Kernel 2: main pass. grid = (32 i-blocks, 16 k-chunks).
// Each thread owns one a-point; warp iterates k over a smem chunk
// (broadcast LDS.128), 3 FFMA + 1 FMNMX per pair; atomicMin merges chunks.
// ---------------------------------------------------------------------------
__global__ void __launch_bounds__(I_BLOCK)
chamfer_min_kernel() {
    __shared__ float4 sb[K_CHUNK];

    const int t  = threadIdx.x;
    const int kbase = blockIdx.y * K_CHUNK;

    // Cooperative load of this k-chunk (8 KB)
    #pragma unroll
    for (int k = t; k < K_CHUNK; k += I_BLOCK) sb[k] = g_pb[kbase + k];
    __syncthreads();

    const int i = blockIdx.x * I_BLOCK + t;
    const float4 pa = g_pa[i];

    // Two independent min accumulators for ILP across the fmin chain
    float m0 = 3.4e38f, m1 = 3.4e38f;

    #pragma unroll 8
    for (int k = 0; k < K_CHUNK; k += 2) {
        float4 b0 = sb[k];
        float4 b1 = sb[k + 1];
        float v0 = fmaf(b0.x, pa.x, b0.w);
        float v1 = fmaf(b1.x, pa.x, b1.w);
        v0 = fmaf(b0.y, pa.y, v0);
        v1 = fmaf(b1.y, pa.y, v1);
        v0 = fmaf(b0.z, pa.z, v0);
        v1 = fmaf(b1.z, pa.z, v1);
        m0 = fminf(m0, v0);
        m1 = fminf(m1, v1);
    }
    float m = fminf(m0, m1);

    atomicMin(&g_minkey[i], fkey(m));
}

// ---------------------------------------------------------------------------
// Kernel 3: decode mins, add ||a||^2, sum -> scalar. Double accumulation.
// ---------------------------------------------------------------------------
__global__ void reduce_kernel(float* __restrict__ out) {
    __shared__ double warp_sums[16];
    const int t = threadIdx.x;        // 512 threads = 16 warps
    double s = 0.0;
    for (int i = t; i < N_SAMPLES; i += 512) {
        s += (double)g_pa[i].w + (double)funkey(g_minkey[i]);
    }
    // warp reduce
    #pragma unroll
    for (int off = 16; off > 0; off >>= 1)
        s += __shfl_down_sync(0xFFFFFFFFu, s, off);
    if ((t & 31) == 0) warp_sums[t >> 5] = s;
    __syncthreads();
    if (t < 32) {
        double v = (t < 16) ? warp_sums[t] : 0.0;
        #pragma unroll
        for (int off = 8; off > 0; off >>= 1)
            v += __shfl_down_sync(0xFFFFFFFFu, v, off);
        if (t == 0) out[0] = (float)v;
    }
}

// ---------------------------------------------------------------------------
extern "C" void kernel_launch(void* const* d_in, const int* in_sizes, int n_in,
                              void* d_out, int out_size) {
    const float* a     = (const float*)d_in[0];
    const float* b     = (const float*)d_in[1];
    const int*   a_idx = (const int*)d_in[2];
    const int*   b_idx = (const int*)d_in[3];
    float* out = (float*)d_out;

    int n_points = in_sizes[0] / 3;   // 16384

    gather_init_kernel<<<(N_SAMPLES + 255) / 256, 256>>>(a, b, a_idx, b_idx, n_points);
    chamfer_min_kernel<<<dim3(N_IBLK, N_KBLK), I_BLOCK>>>();
    reduce_kernel<<<1, 512>>>(out);
}

// round 6
// speedup vs baseline: 2.0479x; 2.0479x over previous
#include <cuda_runtime.h>
#include <cstdint>

// Problem constants (fixed shapes per reference)
#define N_SAMPLES 8192
#define I_BLOCK   256     // a-points per CTA (1 per thread)
#define K_CHUNK   512     // b-points per CTA chunk
#define N_IBLK    (N_SAMPLES / I_BLOCK)   // 32
#define N_KBLK    (N_SAMPLES / K_CHUNK)   // 16
#define N_CTAS    (N_IBLK * N_KBLK)       // 512

// Scratch (no allocations allowed).
// g_soa layout: [0..8191]=-2bx, [8192..]= -2by, [16384..]=-2bz, [24576..]=||b||^2
__device__ float    g_soa[4 * N_SAMPLES];
__device__ float4   g_pa[N_SAMPLES];     // (ax, ay, az, ||a||^2)
__device__ unsigned g_minkey[N_SAMPLES];
__device__ unsigned g_done;

// Packed f32x2 FMA (Blackwell FFMA2) — only reachable via PTX.
#define FMA2(d, a, b, c) \
    asm("fma.rn.f32x2 %0, %1, %2, %3;" : "=l"(d) : "l"(a), "l"(b), "l"(c))
#define PACK2(d, f) \
    asm("mov.b64 %0, {%1, %1};" : "=l"(d) : "f"(f))
#define UNPACK2(lo, hi, v) \
    asm("mov.b64 {%0, %1}, %2;" : "=f"(lo), "=f"(hi) : "l"(v))

// Monotone uint key for float (total order matches float <, incl. negatives)
__device__ __forceinline__ unsigned fkey(float f) {
    unsigned u = __float_as_uint(f);
    return (u & 0x80000000u) ? ~u : (u | 0x80000000u);
}
__device__ __forceinline__ float funkey(unsigned k) {
    unsigned u = (k & 0x80000000u) ? (k & 0x7FFFFFFFu) : ~k;
    return __uint_as_float(u);
}

// ---------------------------------------------------------------------------
// Kernel 1: gather sampled points into SoA form, init min keys + done counter.
// 128 CTAs x 64 threads to spread the scattered LDGs over many SMs.
// ---------------------------------------------------------------------------
__global__ void gather_init_kernel(const float* __restrict__ a,
                                   const float* __restrict__ b,
                                   const int* __restrict__ a_idx,
                                   const int* __restrict__ b_idx,
                                   int n_points) {
    int i = blockIdx.x * blockDim.x + threadIdx.x;
    if (i >= N_SAMPLES) return;
    if (i == 0) g_done = 0u;

    int ia = a_idx[i];
    float ax = a[ia];
    float ay = a[n_points + ia];
    float az = a[2 * n_points + ia];
    g_pa[i] = make_float4(ax, ay, az, ax * ax + ay * ay + az * az);

    int ib = b_idx[i];
    float bx = b[ib];
    float by = b[n_points + ib];
    float bz = b[2 * n_points + ib];
    // v(i,k) = ||b_k||^2 - 2 * dot(b_k, a_i)
    g_soa[0 * N_SAMPLES + i] = -2.0f * bx;
    g_soa[1 * N_SAMPLES + i] = -2.0f * by;
    g_soa[2 * N_SAMPLES + i] = -2.0f * bz;
    g_soa[3 * N_SAMPLES + i] = bx * bx + by * by + bz * bz;

    g_minkey[i] = 0xFFFFFFFFu;  // +max key
}

// ---------------------------------------------------------------------------
// Kernel 2: main pass + fused final reduction.
// grid = (32 i-blocks, 16 k-chunks), 256 threads. Each thread owns one
// a-point; inner loop processes 4 b-points via packed FFMA2:
// per 4 pairs: 4x LDS.128 + 6 FFMA2 + 4 FMNMX  (2.5 fma-pipe ops / pair).
// Last-finishing CTA performs the decode+sum.
// ---------------------------------------------------------------------------
__global__ void __launch_bounds__(I_BLOCK)
chamfer_min_kernel(float* __restrict__ out) {
    __shared__ float s[4 * K_CHUNK];          // 8 KB, SoA chunk
    __shared__ float warp_sums[I_BLOCK / 32];
    __shared__ unsigned s_islast;

    const int t = threadIdx.x;
    const int kbase = blockIdx.y * K_CHUNK;

    // Cooperative chunk load: 512 float4 total, 2 per thread.
    #pragma unroll
    for (int q = t; q < 4 * K_CHUNK / 4; q += I_BLOCK) {
        int c = q >> 7;          // component (128 float4 per component)
        int j = q & 127;
        ((float4*)(s + c * K_CHUNK))[j] =
            ((const float4*)(g_soa + c * N_SAMPLES + kbase))[j];
    }
    __syncthreads();

    const int i = blockIdx.x * I_BLOCK + t;
    const float4 pa = g_pa[i];

    unsigned long long pax2, pay2, paz2;
    PACK2(pax2, pa.x);
    PACK2(pay2, pa.y);
    PACK2(paz2, pa.z);

    const longlong2* xs = (const longlong2*)(s);
    const longlong2* ys = (const longlong2*)(s + K_CHUNK);
    const longlong2* zs = (const longlong2*)(s + 2 * K_CHUNK);
    const longlong2* ws = (const longlong2*)(s + 3 * K_CHUNK);

    float m0 = 3.4e38f, m1 = 3.4e38f, m2 = 3.4e38f, m3 = 3.4e38f;

    #pragma unroll 4
    for (int g = 0; g < K_CHUNK / 4; ++g) {
        longlong2 X = xs[g];   // 4 consecutive -2bx values (2 packed f32x2)
        longlong2 Y = ys[g];
        longlong2 Z = zs[g];
        longlong2 W = ws[g];

        unsigned long long v01, v23;
        FMA2(v01, X.x, pax2, W.x);
        FMA2(v23, X.y, pax2, W.y);
        FMA2(v01, Y.x, pay2, v01);
        FMA2(v23, Y.y, pay2, v23);
        FMA2(v01, Z.x, paz2, v01);
        FMA2(v23, Z.y, paz2, v23);

        float a0, a1, a2, a3;
        UNPACK2(a0, a1, v01);
        UNPACK2(a2, a3, v23);
        m0 = fminf(m0, a0);
        m1 = fminf(m1, a1);
        m2 = fminf(m2, a2);
        m3 = fminf(m3, a3);
    }
    float m = fminf(fminf(m0, m1), fminf(m2, m3));

    atomicMin(&g_minkey[i], fkey(m));

    // ---- completion counter: last CTA does the final reduction ----
    __threadfence();
    __syncthreads();
    if (t == 0) {
        unsigned c = atomicAdd(&g_done, 1u);
        s_islast = (c == (unsigned)(N_CTAS - 1)) ? 1u : 0u;
    }
    __syncthreads();
    if (!s_islast) return;

    __threadfence();  // acquire: all atomicMin results now visible

    float sum = 0.0f;
    for (int j = t; j < N_SAMPLES; j += I_BLOCK) {
        unsigned kk = ((const volatile unsigned*)g_minkey)[j];  // bypass L1
        sum += g_pa[j].w + funkey(kk);
    }
    // warp reduce
    #pragma unroll
    for (int off = 16; off > 0; off >>= 1)
        sum += __shfl_down_sync(0xFFFFFFFFu, sum, off);
    if ((t & 31) == 0) warp_sums[t >> 5] = sum;
    __syncthreads();
    if (t < 32) {
        float v = (t < I_BLOCK / 32) ? warp_sums[t] : 0.0f;
        #pragma unroll
        for (int off = 4; off > 0; off >>= 1)
            v += __shfl_down_sync(0xFFFFFFFFu, v, off);
        if (t == 0) out[0] = v;
    }
}

// ---------------------------------------------------------------------------
extern "C" void kernel_launch(void* const* d_in, const int* in_sizes, int n_in,
                              void* d_out, int out_size) {
    const float* a     = (const float*)d_in[0];
    const float* b     = (const float*)d_in[1];
    const int*   a_idx = (const int*)d_in[2];
    const int*   b_idx = (const int*)d_in[3];
    float* out = (float*)d_out;

    int n_points = in_sizes[0] / 3;   // 16384

    gather_init_kernel<<<128, 64>>>(a, b, a_idx, b_idx, n_points);
    chamfer_min_kernel<<<dim3(N_IBLK, N_KBLK), I_BLOCK>>>(out);
}

// round 7
// speedup vs baseline: 2.6401x; 1.2892x over previous
#include <cuda_runtime.h>
#include <cstdint>

// Problem constants (fixed shapes per reference)
#define N_SAMPLES 8192
#define I_BLOCK   256                 // threads per CTA
#define IPT       4                   // a-points per thread (register tile)
#define I_TILE    (I_BLOCK * IPT)     // 1024 a-points per CTA
#define K_CHUNK   128                 // b-points per CTA chunk
#define N_IBLK    (N_SAMPLES / I_TILE)    // 8
#define N_KBLK    (N_SAMPLES / K_CHUNK)   // 64
#define N_CTAS    (N_IBLK * N_KBLK)       // 512

// Scratch (no allocations allowed).
// g_soa layout: [0..8191]=-2bx, [8192..]=-2by, [16384..]=-2bz, [24576..]=||b||^2
__device__ float    g_soa[4 * N_SAMPLES];
__device__ float4   g_pa[N_SAMPLES];     // (ax, ay, az, ||a||^2)
__device__ unsigned g_minkey[N_SAMPLES];
__device__ unsigned g_done;

// Packed f32x2 FMA (Blackwell FFMA2) — only reachable via PTX.
#define FMA2(d, a, b, c) \
    asm("fma.rn.f32x2 %0, %1, %2, %3;" : "=l"(d) : "l"(a), "l"(b), "l"(c))
#define PACK2(d, f) \
    asm("mov.b64 %0, {%1, %1};" : "=l"(d) : "f"(f))
#define UNPACK2(lo, hi, v) \
    asm("mov.b64 {%0, %1}, %2;" : "=f"(lo), "=f"(hi) : "l"(v))

// Monotone uint key for float (total order matches float <, incl. negatives)
__device__ __forceinline__ unsigned fkey(float f) {
    unsigned u = __float_as_uint(f);
    return (u & 0x80000000u) ? ~u : (u | 0x80000000u);
}
__device__ __forceinline__ float funkey(unsigned k) {
    unsigned u = (k & 0x80000000u) ? (k & 0x7FFFFFFFu) : ~k;
    return __uint_as_float(u);
}

// ---------------------------------------------------------------------------
// Kernel 1: gather sampled points into SoA form, init min keys + done counter.
// ---------------------------------------------------------------------------
__global__ void gather_init_kernel(const float* __restrict__ a,
                                   const float* __restrict__ b,
                                   const int* __restrict__ a_idx,
                                   const int* __restrict__ b_idx,
                                   int n_points) {
    int i = blockIdx.x * blockDim.x + threadIdx.x;
    if (i >= N_SAMPLES) return;
    if (i == 0) g_done = 0u;

    int ia = a_idx[i];
    float ax = a[ia];
    float ay = a[n_points + ia];
    float az = a[2 * n_points + ia];
    g_pa[i] = make_float4(ax, ay, az, ax * ax + ay * ay + az * az);

    int ib = b_idx[i];
    float bx = b[ib];
    float by = b[n_points + ib];
    float bz = b[2 * n_points + ib];
    // v(i,k) = ||b_k||^2 - 2 * dot(b_k, a_i)
    g_soa[0 * N_SAMPLES + i] = -2.0f * bx;
    g_soa[1 * N_SAMPLES + i] = -2.0f * by;
    g_soa[2 * N_SAMPLES + i] = -2.0f * bz;
    g_soa[3 * N_SAMPLES + i] = bx * bx + by * by + bz * bz;

    g_minkey[i] = 0xFFFFFFFFu;  // +max key
}

// ---------------------------------------------------------------------------
// Kernel 2: main pass + fused final reduction.
// grid = (8 i-blocks, 64 k-chunks), 256 threads. Each thread owns FOUR
// a-points (register tile); inner loop processes 4 b-points via packed FFMA2.
// Per 16 pairs: 4 LDS.128 + 24 FFMA2 + 16 FMNMX  (0.25 LDS / pair).
// atomicMin with unused return compiles to REDG.MIN (no scoreboard wait).
// Last-finishing CTA performs the decode+sum.
// ---------------------------------------------------------------------------
__global__ void __launch_bounds__(I_BLOCK)
chamfer_min_kernel(float* __restrict__ out) {
    __shared__ float s[4 * K_CHUNK];          // 2 KB, SoA chunk
    __shared__ float warp_sums[I_BLOCK / 32];
    __shared__ unsigned s_islast;

    const int t = threadIdx.x;
    const int kbase = blockIdx.y * K_CHUNK;
    const int ibase = blockIdx.x * I_TILE;

    // Cooperative chunk load: 128 float4 total (threads 0..127, one each).
    if (t < 128) {
        int c = t >> 5;          // component (32 float4 per component)
        int j = t & 31;
        ((float4*)(s + c * K_CHUNK))[j] =
            ((const float4*)(g_soa + c * N_SAMPLES + kbase))[j];
    }
    __syncthreads();

    // Load 4 a-points (coalesced: stride I_BLOCK)
    unsigned long long pax2[IPT], pay2[IPT], paz2[IPT];
    #pragma unroll
    for (int j = 0; j < IPT; ++j) {
        float4 pa = g_pa[ibase + j * I_BLOCK + t];
        PACK2(pax2[j], pa.x);
        PACK2(pay2[j], pa.y);
        PACK2(paz2[j], pa.z);
    }

    const longlong2* xs = (const longlong2*)(s);
    const longlong2* ys = (const longlong2*)(s + K_CHUNK);
    const longlong2* zs = (const longlong2*)(s + 2 * K_CHUNK);
    const longlong2* ws = (const longlong2*)(s + 3 * K_CHUNK);

    float mA[IPT], mB[IPT];
    #pragma unroll
    for (int j = 0; j < IPT; ++j) { mA[j] = 3.4e38f; mB[j] = 3.4e38f; }

    #pragma unroll 2
    for (int g = 0; g < K_CHUNK / 4; ++g) {
        longlong2 X = xs[g];   // 4 consecutive -2bx values (2 packed f32x2)
        longlong2 Y = ys[g];
        longlong2 Z = zs[g];
        longlong2 W = ws[g];

        #pragma unroll
        for (int j = 0; j < IPT; ++j) {
            unsigned long long v01, v23;
            FMA2(v01, X.x, pax2[j], W.x);
            FMA2(v23, X.y, pax2[j], W.y);
            FMA2(v01, Y.x, pay2[j], v01);
            FMA2(v23, Y.y, pay2[j], v23);
            FMA2(v01, Z.x, paz2[j], v01);
            FMA2(v23, Z.y, paz2[j], v23);

            float a0, a1, a2, a3;
            UNPACK2(a0, a1, v01);
            UNPACK2(a2, a3, v23);
            mA[j] = fminf(mA[j], fminf(a0, a1));
            mB[j] = fminf(mB[j], fminf(a2, a3));
        }
    }

    #pragma unroll
    for (int j = 0; j < IPT; ++j) {
        float m = fminf(mA[j], mB[j]);
        atomicMin(&g_minkey[ibase + j * I_BLOCK + t], fkey(m));  // -> REDG.MIN
    }

    // ---- completion counter: last CTA does the final reduction ----
    __threadfence();
    __syncthreads();
    if (t == 0) {
        unsigned c = atomicAdd(&g_done, 1u);
        s_islast = (c == (unsigned)(N_CTAS - 1)) ? 1u : 0u;
    }
    __syncthreads();
    if (!s_islast) return;

    __threadfence();  // acquire: all REDG.MIN results now visible

    float sum = 0.0f;
    for (int j = t; j < N_SAMPLES; j += I_BLOCK) {
        unsigned kk = ((const volatile unsigned*)g_minkey)[j];  // bypass L1
        sum += g_pa[j].w + funkey(kk);
    }
    // warp reduce
    #pragma unroll
    for (int off = 16; off > 0; off >>= 1)
        sum += __shfl_down_sync(0xFFFFFFFFu, sum, off);
    if ((t & 31) == 0) warp_sums[t >> 5] = sum;
    __syncthreads();
    if (t < 32) {
        float v = (t < I_BLOCK / 32) ? warp_sums[t] : 0.0f;
        #pragma unroll
        for (int off = 4; off > 0; off >>= 1)
            v += __shfl_down_sync(0xFFFFFFFFu, v, off);
        if (t == 0) out[0] = v;
    }
}

// ---------------------------------------------------------------------------
extern "C" void kernel_launch(void* const* d_in, const int* in_sizes, int n_in,
                              void* d_out, int out_size) {
    const float* a     = (const float*)d_in[0];
    const float* b     = (const float*)d_in[1];
    const int*   a_idx = (const int*)d_in[2];
    const int*   b_idx = (const int*)d_in[3];
    float* out = (float*)d_out;

    int n_points = in_sizes[0] / 3;   // 16384

    gather_init_kernel<<<128, 64>>>(a, b, a_idx, b_idx, n_points);
    chamfer_min_kernel<<<dim3(N_IBLK, N_KBLK), I_BLOCK>>>(out);
}

// round 8
// speedup vs baseline: 2.8691x; 1.0867x over previous
#include <cuda_runtime.h>
#include <cstdint>

// Problem constants (fixed shapes per reference)
#define N_SAMPLES 8192
#define I_BLOCK   256                 // threads per CTA
#define IPT       4                   // a-points per thread (register tile)
#define I_TILE    (I_BLOCK * IPT)     // 1024 a-points per CTA
#define K_CHUNK   64                  // b-points per CTA chunk
#define N_IBLK    (N_SAMPLES / I_TILE)    // 8
#define N_KBLK    (N_SAMPLES / K_CHUNK)   // 128
#define N_CTAS    (N_IBLK * N_KBLK)       // 1024

// Scratch (no allocations allowed).
// g_soa layout: [0..8191]=-2bx, [8192..]=-2by, [16384..]=-2bz, [24576..]=||b||^2
__device__ float    g_soa[4 * N_SAMPLES];
__device__ float4   g_pa[N_SAMPLES];     // (ax, ay, az, ||a||^2)
__device__ unsigned g_minkey[N_SAMPLES];
__device__ unsigned g_done;

// Packed f32x2 FMA (Blackwell FFMA2) — only reachable via PTX.
#define FMA2(d, a, b, c) \
    asm("fma.rn.f32x2 %0, %1, %2, %3;" : "=l"(d) : "l"(a), "l"(b), "l"(c))
#define PACK2(d, f) \
    asm("mov.b64 %0, {%1, %1};" : "=l"(d) : "f"(f))
#define UNPACK2(lo, hi, v) \
    asm("mov.b64 {%0, %1}, %2;" : "=f"(lo), "=f"(hi) : "l"(v))

// Monotone uint key for float (total order matches float <, incl. negatives)
__device__ __forceinline__ unsigned fkey(float f) {
    unsigned u = __float_as_uint(f);
    return (u & 0x80000000u) ? ~u : (u | 0x80000000u);
}
__device__ __forceinline__ float funkey(unsigned k) {
    unsigned u = (k & 0x80000000u) ? (k & 0x7FFFFFFFu) : ~k;
    return __uint_as_float(u);
}

// ---------------------------------------------------------------------------
// Kernel 1: gather sampled points into SoA form, init min keys + done counter.
// ---------------------------------------------------------------------------
__global__ void gather_init_kernel(const float* __restrict__ a,
                                   const float* __restrict__ b,
                                   const int* __restrict__ a_idx,
                                   const int* __restrict__ b_idx,
                                   int n_points) {
    int i = blockIdx.x * blockDim.x + threadIdx.x;
    if (i >= N_SAMPLES) return;
    if (i == 0) g_done = 0u;

    int ia = a_idx[i];
    float ax = a[ia];
    float ay = a[n_points + ia];
    float az = a[2 * n_points + ia];
    g_pa[i] = make_float4(ax, ay, az, ax * ax + ay * ay + az * az);

    int ib = b_idx[i];
    float bx = b[ib];
    float by = b[n_points + ib];
    float bz = b[2 * n_points + ib];
    // v(i,k) = ||b_k||^2 - 2 * dot(b_k, a_i)
    g_soa[0 * N_SAMPLES + i] = -2.0f * bx;
    g_soa[1 * N_SAMPLES + i] = -2.0f * by;
    g_soa[2 * N_SAMPLES + i] = -2.0f * bz;
    g_soa[3 * N_SAMPLES + i] = bx * bx + by * by + bz * bz;

    g_minkey[i] = 0xFFFFFFFFu;  // +max key
}

// ---------------------------------------------------------------------------
// Kernel 2: main pass + fused final reduction.
// grid = (8 i-blocks, 128 k-chunks) = 1024 CTAs to fill 5 CTAs/SM.
// Each thread owns FOUR a-points (register tile); inner loop processes 4
// b-points via packed FFMA2. Per 16 pairs: 4 LDS.128 + 24 FFMA2 + 16 FMNMX.
// atomicMin with unused return compiles to REDG.MIN (no scoreboard wait).
// Last-finishing CTA performs the decode+sum.
// ---------------------------------------------------------------------------
__global__ void __launch_bounds__(I_BLOCK)
chamfer_min_kernel(float* __restrict__ out) {
    __shared__ float s[4 * K_CHUNK];          // 1 KB, SoA chunk
    __shared__ float warp_sums[I_BLOCK / 32];
    __shared__ unsigned s_islast;

    const int t = threadIdx.x;
    const int kbase = blockIdx.y * K_CHUNK;
    const int ibase = blockIdx.x * I_TILE;

    // Cooperative chunk load: 64 float4 total (threads 0..63, one each).
    if (t < 64) {
        int c = t >> 4;          // component (16 float4 per component)
        int j = t & 15;
        ((float4*)(s + c * K_CHUNK))[j] =
            ((const float4*)(g_soa + c * N_SAMPLES + kbase))[j];
    }
    __syncthreads();

    // Load 4 a-points (coalesced: stride I_BLOCK)
    unsigned long long pax2[IPT], pay2[IPT], paz2[IPT];
    #pragma unroll
    for (int j = 0; j < IPT; ++j) {
        float4 pa = g_pa[ibase + j * I_BLOCK + t];
        PACK2(pax2[j], pa.x);
        PACK2(pay2[j], pa.y);
        PACK2(paz2[j], pa.z);
    }

    const longlong2* xs = (const longlong2*)(s);
    const longlong2* ys = (const longlong2*)(s + K_CHUNK);
    const longlong2* zs = (const longlong2*)(s + 2 * K_CHUNK);
    const longlong2* ws = (const longlong2*)(s + 3 * K_CHUNK);

    float mA[IPT], mB[IPT];
    #pragma unroll
    for (int j = 0; j < IPT; ++j) { mA[j] = 3.4e38f; mB[j] = 3.4e38f; }

    #pragma unroll 4
    for (int g = 0; g < K_CHUNK / 4; ++g) {
        longlong2 X = xs[g];   // 4 consecutive -2bx values (2 packed f32x2)
        longlong2 Y = ys[g];
        longlong2 Z = zs[g];
        longlong2 W = ws[g];

        #pragma unroll
        for (int j = 0; j < IPT; ++j) {
            unsigned long long v01, v23;
            FMA2(v01, X.x, pax2[j], W.x);
            FMA2(v23, X.y, pax2[j], W.y);
            FMA2(v01, Y.x, pay2[j], v01);
            FMA2(v23, Y.y, pay2[j], v23);
            FMA2(v01, Z.x, paz2[j], v01);
            FMA2(v23, Z.y, paz2[j], v23);

            float a0, a1, a2, a3;
            UNPACK2(a0, a1, v01);
            UNPACK2(a2, a3, v23);
            mA[j] = fminf(mA[j], fminf(a0, a1));
            mB[j] = fminf(mB[j], fminf(a2, a3));
        }
    }

    #pragma unroll
    for (int j = 0; j < IPT; ++j) {
        float m = fminf(mA[j], mB[j]);
        atomicMin(&g_minkey[ibase + j * I_BLOCK + t], fkey(m));  // -> REDG.MIN
    }

    // ---- completion counter: last CTA does the final reduction ----
    __threadfence();
    __syncthreads();
    if (t == 0) {
        unsigned c = atomicAdd(&g_done, 1u);
        s_islast = (c == (unsigned)(N_CTAS - 1)) ? 1u : 0u;
    }
    __syncthreads();
    if (!s_islast) return;

    __threadfence();  // acquire: all REDG.MIN results now visible

    float sum = 0.0f;
    for (int j = t; j < N_SAMPLES; j += I_BLOCK) {
        unsigned kk = ((const volatile unsigned*)g_minkey)[j];  // bypass L1
        sum += g_pa[j].w + funkey(kk);
    }
    // warp reduce
    #pragma unroll
    for (int off = 16; off > 0; off >>= 1)
        sum += __shfl_down_sync(0xFFFFFFFFu, sum, off);
    if ((t & 31) == 0) warp_sums[t >> 5] = sum;
    __syncthreads();
    if (t < 32) {
        float v = (t < I_BLOCK / 32) ? warp_sums[t] : 0.0f;
        #pragma unroll
        for (int off = 4; off > 0; off >>= 1)
            v += __shfl_down_sync(0xFFFFFFFFu, v, off);
        if (t == 0) out[0] = v;
    }
}

// ---------------------------------------------------------------------------
extern "C" void kernel_launch(void* const* d_in, const int* in_sizes, int n_in,
                              void* d_out, int out_size) {
    const float* a     = (const float*)d_in[0];
    const float* b     = (const float*)d_in[1];
    const int*   a_idx = (const int*)d_in[2];
    const int*   b_idx = (const int*)d_in[3];
    float* out = (float*)d_out;

    int n_points = in_sizes[0] / 3;   // 16384

    gather_init_kernel<<<128, 64>>>(a, b, a_idx, b_idx, n_points);
    chamfer_min_kernel<<<dim3(N_IBLK, N_KBLK), I_BLOCK>>>(out);
}